// round 11
// baseline (speedup 1.0000x reference)
#include <cuda_runtime.h>
#include <cstdint>

// Fixed shapes
#define TT 1024
#define BB 8
#define HH 8
#define NN 32
#define DEPTH 4
#define ROWP 36                 // padded row stride (144B): 16B-aligned
#define SLOT (NN * ROWP)
#define SLOTB (SLOT * 4)

__device__ __forceinline__ void cp16(uint32_t d, const void* s) {
    asm volatile("cp.async.cg.shared.global [%0], [%1], 16;\n" :: "r"(d), "l"(s) : "memory");
}
__device__ __forceinline__ void cpcommit() {
    asm volatile("cp.async.commit_group;\n" ::: "memory");
}
template<int N> __device__ __forceinline__ void cpwait() {
    asm volatile("cp.async.wait_group %0;\n" :: "n"(N) : "memory");
}
__device__ __forceinline__ float ex2f(float x) { float y; asm("ex2.approx.f32 %0, %1;" : "=f"(y) : "f"(x)); return y; }
__device__ __forceinline__ float rcpf(float x) { float y; asm("rcp.approx.f32 %0, %1;" : "=f"(y) : "f"(x)); return y; }
__device__ __forceinline__ float sqrtaf(float x){ float y; asm("sqrt.approx.f32 %0, %1;" : "=f"(y) : "f"(x)); return y; }

// tanh(y) = 2/(1+exp(-2y)) - 1 ; exp(-2y) = ex2(C2*y). Limit-safe for all y.
#define C2   (-2.8853900817779268f)   // -2*log2(e)
#define L2E  (1.4426950408889634f)
#define INV32   0.03125f
#define INV1024 0.0009765625f

__global__ __launch_bounds__(128, 1)
void e86_cell_kernel(const float* __restrict__ x,
                     const float* __restrict__ S0,
                     const float* __restrict__ scale_p,
                     const float* __restrict__ bias_p,
                     float* __restrict__ out,
                     int write_sfinal)
{
    __shared__ __align__(16) float ring[DEPTH * SLOT];
    __shared__ float rpart[2][4][NN];   // retrieved partials, parity t&1
    __shared__ float qpart[2][4][NN];   // Sq partials,        parity t&1
    __shared__ float vpart[4][4][NN];   // v partials, slot s&3 (written 2 steps ahead)

    const int tid  = threadIdx.x;
    const int w    = tid >> 5;       // warp owns S COLUMNS [8w, 8w+8)
    const int lane = tid & 31;       // lane = ROW index i
    const int head = blockIdx.x;

    const float scale = scale_p[0];
    const float bias  = bias_p[0];

    const float* xh = x + (size_t)head * (NN * NN);
    const size_t xs = (size_t)(BB * HH * NN * NN);   // 65536 floats per timestep

    // S[j] = S[lane][8w+j]
    float S[8];
    {
        const float* p = S0 + (size_t)head * (NN * NN) + (size_t)lane * NN + 8 * w;
        #pragma unroll
        for (int j = 0; j < 8; j++) S[j] = p[j];
    }

    // cp.async plan: 256 16B chunks/tile, 2 per thread
    const int c0 = tid, c1 = tid + 128;
    const uint32_t sring = (uint32_t)__cvta_generic_to_shared(ring);
    const uint32_t so0 = (uint32_t)((c0 >> 3) * (ROWP * 4) + (c0 & 7) * 16);
    const uint32_t so1 = (uint32_t)((c1 >> 3) * (ROWP * 4) + (c1 & 7) * 16);
    const float* g0 = xh + (c0 >> 3) * NN + (c0 & 7) * 4;
    const float* g1 = xh + (c1 >> 3) * NN + (c1 & 7) * 4;

    // ---- prologue: fill ring with tiles 0..3 ----
    #pragma unroll
    for (int s = 0; s < DEPTH; s++) {
        cp16(sring + s * SLOTB + so0, g0 + (size_t)s * xs);
        cp16(sring + s * SLOTB + so1, g1 + (size_t)s * xs);
        cpcommit();
    }
    cpwait<2>();            // this thread's tile 0,1 chunks done
    __syncthreads();        // all threads' tile 0,1 chunks visible

    // prep(s): from tile in slot s&3 compute kn[8] (this warp's columns), beta,
    // and write the v partial into vpart[s&3]. Tile-only; no recurrence deps.
    auto prep = [&](int s, float* knp, float* betap) {
        const int slot = s & 3;
        const float* T = ring + slot * SLOT;
        const float4* r4 = (const float4*)(T + lane * ROWP);
        float a0 = 0.f, a1 = 0.f, a2 = 0.f, a3 = 0.f;
        #pragma unroll
        for (int c = 0; c < 8; c += 4) {
            float4 q0 = r4[c + 0], q1 = r4[c + 1], q2 = r4[c + 2], q3 = r4[c + 3];
            a0 += (q0.x + q0.y) + (q0.z + q0.w);
            a1 += (q1.x + q1.y) + (q1.z + q1.w);
            a2 += (q2.x + q2.y) + (q2.z + q2.w);
            a3 += (q3.x + q3.y) + (q3.z + q3.w);
        }
        float rowsum = (a0 + a1) + (a2 + a3);
        float klm = rowsum * INV32;                 // k[lane]
        float s1 = rowsum, s2 = klm * klm;
        #pragma unroll
        for (int o = 16; o; o >>= 1) {
            s1 += __shfl_xor_sync(0xffffffffu, s1, o);
            s2 += __shfl_xor_sync(0xffffffffu, s2, o);
        }
        float rn = rcpf(sqrtaf(s2) + 1e-6f);
        *betap = rcpf(1.0f + ex2f(-L2E * fmaf(scale, s1 * INV1024, bias)));
        #pragma unroll
        for (int j = 0; j < 8; j++)
            knp[j] = __shfl_sync(0xffffffffu, klm, 8 * w + j) * rn;
        const float* cb = T + (8 * w) * ROWP + lane;
        vpart[slot][w][lane] = ((cb[0] + cb[ROWP]) + (cb[2 * ROWP] + cb[3 * ROWP]))
                             + ((cb[4 * ROWP] + cb[5 * ROWP]) + (cb[6 * ROWP] + cb[7 * ROWP]));
    };

    float kn_cur[8], kn_nxt[8], beta_cur, beta_nxt;
    prep(0, kn_cur, &beta_cur);
    prep(1, kn_nxt, &beta_nxt);

    // ---- main scan: ONE block barrier per step; prep runs 2 steps ahead ----
    for (int t = 0; t < TT; t++) {
        const int p  = t & 1;
        const int pn = p ^ 1;

        // [chain] retrieved partial (this warp's 8 columns), kn_cur ready early
        {
            float r0 = S[0] * kn_cur[0], r1 = S[1] * kn_cur[1];
            float r2 = S[2] * kn_cur[2], r3 = S[3] * kn_cur[3];
            r0 = fmaf(S[4], kn_cur[4], r0); r1 = fmaf(S[5], kn_cur[5], r1);
            r2 = fmaf(S[6], kn_cur[6], r2); r3 = fmaf(S[7], kn_cur[7], r3);
            rpart[p][w][lane] = (r0 + r1) + (r2 + r3);
        }

        cpwait<1>();          // tile t+2 resident (this thread's chunks)
        __syncthreads();      // BAR(t): rpart[p], vpart[t&3], qpart[pn], tiles visible

        // refill slot t&3 with tile t+4 (last ring read of this slot: prep(t) @ iter t-2)
        if (t + 4 < TT) {
            const uint32_t sb = sring + (uint32_t)(t & 3) * SLOTB;
            cp16(sb + so0, g0 + (size_t)(t + 4) * xs);
            cp16(sb + so1, g1 + (size_t)(t + 4) * xs);
        }
        cpcommit();           // exactly one group per iteration

        // [off-chain] output for step t-1; all 4 warps write 8 rows each
        if (t >= 1 && lane < 8) {
            const int row = 8 * w + lane;
            float q = (qpart[pn][0][row] + qpart[pn][1][row])
                    + (qpart[pn][2][row] + qpart[pn][3][row]);
            float sg = rcpf(1.0f + ex2f(-L2E * q));
            out[(size_t)(t - 1) * (BB * HH * NN) + (size_t)head * NN + row] = q * q * sg;
        }

        // [chain] combine -> delta; tanh -> S_new
        {
            float ret = (rpart[p][0][lane] + rpart[p][1][lane])
                      + (rpart[p][2][lane] + rpart[p][3][lane]);
            const float (*vp)[NN] = vpart[t & 3];
            float vv  = ((vp[0][lane] + vp[1][lane]) + (vp[2][lane] + vp[3][lane])) * INV32;
            float delta = vv - ret;
            float b2 = C2 * beta_cur, d2 = C2 * delta;
            #pragma unroll
            for (int j = 0; j < 8; j++) {
                float z = fmaf(b2, S[j], d2 * kn_cur[j]);
                S[j] = fmaf(2.0f, rcpf(1.0f + ex2f(z)), -1.0f);
            }
        }

        // [off-chain] Sq partial for step t
        {
            float q0 = S[0] * kn_cur[0], q1 = S[1] * kn_cur[1];
            float q2 = S[2] * kn_cur[2], q3 = S[3] * kn_cur[3];
            q0 = fmaf(S[4], kn_cur[4], q0); q1 = fmaf(S[5], kn_cur[5], q1);
            q2 = fmaf(S[6], kn_cur[6], q2); q3 = fmaf(S[7], kn_cur[7], q3);
            qpart[p][w][lane] = (q0 + q1) + (q2 + q3);
        }

        // rotate pipeline state; prep step t+2 (tile resident since BAR(t))
        beta_cur = beta_nxt;
        #pragma unroll
        for (int j = 0; j < 8; j++) kn_cur[j] = kn_nxt[j];
        if (t + 2 < TT) prep(t + 2, kn_nxt, &beta_nxt);
    }

    // tail: output for step TT-1, optional S_final
    __syncthreads();
    {
        const int pl = (TT - 1) & 1;
        if (lane < 8) {
            const int row = 8 * w + lane;
            float q = (qpart[pl][0][row] + qpart[pl][1][row])
                    + (qpart[pl][2][row] + qpart[pl][3][row]);
            float sg = rcpf(1.0f + ex2f(-L2E * q));
            out[(size_t)(TT - 1) * (BB * HH * NN) + (size_t)head * NN + row] = q * q * sg;
        }
    }
    if (write_sfinal) {
        float* dst = out + (size_t)TT * (BB * HH * NN)
                   + (size_t)head * (NN * NN) + (size_t)lane * NN + 8 * w;
        #pragma unroll
        for (int j = 0; j < 8; j++) dst[j] = S[j];
    }
}

extern "C" void kernel_launch(void* const* d_in, const int* in_sizes, int n_in,
                              void* d_out, int out_size)
{
    const float* x       = (const float*)d_in[0];
    const float* S0      = (const float*)d_in[1];
    const float* scale_p = (const float*)d_in[2];
    const float* bias_p  = (const float*)d_in[3];
    float* out = (float*)d_out;

    const int out_main = TT * BB * HH * NN;              // 2,097,152
    const int out_full = out_main + BB * HH * NN * NN;   // 2,162,688
    const int write_sfinal = (out_size >= out_full) ? 1 : 0;

    e86_cell_kernel<<<BB * HH, 128>>>(x, S0, scale_p, bias_p, out, write_sfinal);
}